// round 2
// baseline (speedup 1.0000x reference)
#include <cuda_runtime.h>
#include <cuda_bf16.h>
#include <cstdint>

// Problem constants
#define Nn   8
#define Cc   256
#define Hh   64
#define Ww   64
#define HWp  4096          // H*W
#define Gr   8             // groups
#define KK2  9             // K*K
#define GKK  72            // G*K*K
#define HIDc 256
#define HCc  16
#define NCHW (8*256*4096)

// ---------------- scratch (device globals: no allocation allowed) ----------------
__device__ float  g_gap[2][Nn][Cc];        // per-modality GAP
__device__ float  g_filt[2][Nn][GKK];      // softmaxed dynamic filters
__device__ float2 g_wAB[2][Nn][Cc];        // (wR - wT, wT) gating per channel
__device__ float  g_F[2][Nn][HCc][HWp];    // Rf (mod 0) / Tf (mod 1), 16-ch features
__device__ float  g_wG[Nn][HCc];           // global gate

// ---------------- Kernel 1: GAP over H,W (+ copy R to output) ----------------
__global__ void k_gap(const float* __restrict__ R, const float* __restrict__ T,
                      float* __restrict__ outR)
{
    int b   = blockIdx.x;          // 0..4095 : mod*2048 + (n*256+c)
    int mod = b >> 11;
    int nc  = b & 2047;
    const float4* p = (const float4*)((mod ? T : R) + (size_t)nc * HWp);
    float4* q = (mod == 0 && outR) ? (float4*)(outR + (size_t)nc * HWp) : nullptr;
    int t = threadIdx.x;           // 128 threads
    float s = 0.f;
#pragma unroll
    for (int i = 0; i < 8; i++) {
        float4 v = p[t + 128 * i];
        if (q) q[t + 128 * i] = v;
        s += v.x + v.y + v.z + v.w;
    }
#pragma unroll
    for (int o = 16; o; o >>= 1) s += __shfl_down_sync(0xffffffffu, s, o);
    __shared__ float sm[4];
    if ((t & 31) == 0) sm[t >> 5] = s;
    __syncthreads();
    if (t == 0)
        g_gap[mod][nc >> 8][nc & 255] = (sm[0] + sm[1] + sm[2] + sm[3]) * (1.f / 4096.f);
}

// ---------------- Kernel 2: per-sample filters + gating MLPs ----------------
__global__ void k_vec(const float* __restrict__ conv_w,
                      const float* __restrict__ bn_g, const float* __restrict__ bn_b,
                      const float* __restrict__ bn_m, const float* __restrict__ bn_v,
                      const float* __restrict__ f1W1, const float* __restrict__ f1b1,
                      const float* __restrict__ f1W2R, const float* __restrict__ f1b2R,
                      const float* __restrict__ f1W2T, const float* __restrict__ f1b2T,
                      const float* __restrict__ f2W1, const float* __restrict__ f2b1,
                      const float* __restrict__ f2W2R, const float* __restrict__ f2b2R,
                      const float* __restrict__ f2W2T, const float* __restrict__ f2b2T)
{
    int mod = blockIdx.x >> 3, n = blockIdx.x & 7;
    const float* W1  = mod ? f2W1  : f1W1;
    const float* b1  = mod ? f2b1  : f1b1;
    const float* W2R = mod ? f2W2R : f1W2R;
    const float* b2R = mod ? f2b2R : f1b2R;
    const float* W2T = mod ? f2W2T : f1W2T;
    const float* b2T = mod ? f2b2T : f1b2T;

    __shared__ float gp[Cc], hid[HIDc], lf[GKK];
    int t = threadIdx.x;   // 256
    gp[t] = g_gap[mod][n][t];
    __syncthreads();

    if (t < GKK) {         // dynamic filter logits + BN
        float a = 0.f;
        for (int i = 0; i < Cc; i++) a += gp[i] * conv_w[t * Cc + i];
        a = (a - bn_m[t]) * rsqrtf(bn_v[t] + 1e-5f) * bn_g[t] + bn_b[t];
        lf[t] = a;
    }
    float a = b1[t];       // hidden layer (uses gap directly: (fl+fh).mean == gap)
    for (int i = 0; i < Cc; i++) a += gp[i] * W1[i * HIDc + t];
    hid[t] = fmaxf(a, 0.f);
    __syncthreads();

    if (t < Gr) {          // softmax over each group of 9
        float mx = -1e30f;
#pragma unroll
        for (int k = 0; k < KK2; k++) mx = fmaxf(mx, lf[t * KK2 + k]);
        float e[KK2], sum = 0.f;
#pragma unroll
        for (int k = 0; k < KK2; k++) { e[k] = expf(lf[t * KK2 + k] - mx); sum += e[k]; }
        float inv = 1.f / sum;
#pragma unroll
        for (int k = 0; k < KK2; k++) g_filt[mod][n][t * KK2 + k] = e[k] * inv;
    }
    float aR = b2R[t], aT = b2T[t];
    for (int i = 0; i < HIDc; i++) {
        float h = hid[i];
        aR += h * W2R[i * Cc + t];
        aT += h * W2T[i * Cc + t];
    }
    float wR = 1.f / (1.f + expf(-aR));
    float wT = 1.f / (1.f + expf(-aT));
    g_wAB[mod][n][t] = make_float2(wR - wT, wT);
}

// ---------------- Kernel 3: involution + gating + 256->16 conv (fused) ----------------
// grid = 128: mod*64 + n*8 + tile; tile: 2 (y) x 4 (x) of 32x16 pixel tiles.
// 256 threads, each owns 2 vertically-adjacent pixels. Double-buffered halo tile.
#define TSTRIDE 24   // smem row stride (34 rows x 24) -> conflict-free across tyP pairs
__global__ void __launch_bounds__(256) k_main(const float* __restrict__ R,
                                              const float* __restrict__ T,
                                              const float* __restrict__ fv_wR,
                                              const float* __restrict__ fv_bR,
                                              const float* __restrict__ fv_wT,
                                              const float* __restrict__ fv_bT)
{
    int b   = blockIdx.x;
    int mod = b >> 6;
    int r   = b & 63;
    int n   = r >> 3;
    int tile = r & 7;
    int ty0 = (tile >> 2) * 32;
    int tx0 = (tile & 3) * 16;

    const float* X    = (mod ? T : R) + (size_t)n * Cc * HWp;
    const float* wmat = mod ? fv_wT : fv_wR;
    const float* bias = mod ? fv_bT : fv_bR;
    float* Out = &g_F[mod][n][0][0];

    __shared__ float  buf[2][34 * TSTRIDE];
    __shared__ float  wv[Cc * HCc];        // transposed: wv[c*16+o]
    __shared__ float2 ab_sm[Cc];
    __shared__ float  filt_sm[GKK];

    int t = threadIdx.x;
    for (int i = t; i < Cc * HCc; i += 256) {
        int o = i >> 8, c = i & 255;
        wv[c * HCc + o] = wmat[i];
    }
    ab_sm[t] = g_wAB[mod][n][t];
    if (t < GKK) filt_sm[t] = g_filt[mod][n][t];

    // precompute halo slots (34 rows x 18 cols = 612 loads)
    int goff[3], soff[3];
    bool has[3];
#pragma unroll
    for (int s = 0; s < 3; s++) {
        int idx = t + 256 * s;
        has[s] = idx < 612;
        int rr = idx / 18, qq = idx - rr * 18;
        int gy = ty0 - 1 + rr; gy = gy < 0 ? -gy : (gy > 63 ? 126 - gy : gy);
        int gx = tx0 - 1 + qq; gx = gx < 0 ? -gx : (gx > 63 ? 126 - gx : gx);
        goff[s] = gy * Ww + gx;
        soff[s] = rr * TSTRIDE + qq;
    }
    int tx = t & 15;
    int l  = (t >> 4) * 2;     // local y of first pixel (even)

    float acc0[HCc], acc1[HCc];
#pragma unroll
    for (int i = 0; i < HCc; i++) { acc0[i] = 0.f; acc1[i] = 0.f; }

    {   // preload channel 0
        const float* Xc = X;
#pragma unroll
        for (int s = 0; s < 3; s++) if (has[s]) buf[0][soff[s]] = Xc[goff[s]];
    }
    __syncthreads();

    float f[KK2];
    for (int c = 0; c < Cc; c++) {
        int p = c & 1;
        if (c + 1 < Cc) {
            const float* Xc = X + (size_t)(c + 1) * HWp;
#pragma unroll
            for (int s = 0; s < 3; s++) if (has[s]) buf[p ^ 1][soff[s]] = Xc[goff[s]];
        }
        if ((c & 31) == 0) {
            int g = c >> 5;
#pragma unroll
            for (int k = 0; k < KK2; k++) f[k] = filt_sm[g * KK2 + k];
        }
        float2 ab = ab_sm[c];
        const float* w0 = &buf[p][l * TSTRIDE + tx];
        float v00 = w0[0],           v01 = w0[1],           v02 = w0[2];
        float v10 = w0[TSTRIDE],     v11 = w0[TSTRIDE + 1], v12 = w0[TSTRIDE + 2];
        float v20 = w0[2 * TSTRIDE], v21 = w0[2 * TSTRIDE + 1], v22 = w0[2 * TSTRIDE + 2];
        float v30 = w0[3 * TSTRIDE], v31 = w0[3 * TSTRIDE + 1], v32 = w0[3 * TSTRIDE + 2];
        float low0 = f[0]*v00 + f[1]*v01 + f[2]*v02
                   + f[3]*v10 + f[4]*v11 + f[5]*v12
                   + f[6]*v20 + f[7]*v21 + f[8]*v22;
        float low1 = f[0]*v10 + f[1]*v11 + f[2]*v12
                   + f[3]*v20 + f[4]*v21 + f[5]*v22
                   + f[6]*v30 + f[7]*v31 + f[8]*v32;
        float val0 = ab.y * v11 + ab.x * low0;   // wT*X + (wR-wT)*low
        float val1 = ab.y * v21 + ab.x * low1;
        const float4* wp = (const float4*)&wv[c * HCc];
#pragma unroll
        for (int q = 0; q < 4; q++) {
            float4 w = wp[q];
            acc0[q*4+0] += w.x * val0; acc0[q*4+1] += w.y * val0;
            acc0[q*4+2] += w.z * val0; acc0[q*4+3] += w.w * val0;
            acc1[q*4+0] += w.x * val1; acc1[q*4+1] += w.y * val1;
            acc1[q*4+2] += w.z * val1; acc1[q*4+3] += w.w * val1;
        }
        __syncthreads();
    }
    int y0 = ty0 + l, x = tx0 + tx;
#pragma unroll
    for (int hc = 0; hc < HCc; hc++) {
        float bb = bias[hc];
        Out[hc * HWp + y0 * Ww + x]       = acc0[hc] + bb;
        Out[hc * HWp + (y0 + 1) * Ww + x] = acc1[hc] + bb;
    }
}

// ---------------- Kernel 4: Gf mean + wG ----------------
__global__ void k_wg(const float* __restrict__ Lw, const float* __restrict__ Lb)
{
    int n = blockIdx.x;
    int t = threadIdx.x;            // 256
    int hc = t >> 4, p = t & 15;
    const float* a = &g_F[0][n][hc][0];
    const float* b = &g_F[1][n][hc][0];
    float s = 0.f;
    for (int i = p; i < HWp; i += 16) s += a[i] + b[i];
#pragma unroll
    for (int o = 8; o; o >>= 1) s += __shfl_down_sync(0xffffffffu, s, o, 16);
    __shared__ float mean[HCc];
    if (p == 0) mean[hc] = s * (1.f / 4096.f);
    __syncthreads();
    if (t < HCc) {
        float a2 = Lb[t];
#pragma unroll
        for (int i = 0; i < HCc; i++) a2 += mean[i] * Lw[i * HCc + t];
        g_wG[n][t] = 1.f / (1.f + expf(-a2));
    }
}

// ---------------- Kernel 5: fovea softmax (over W) + 16->256 conv ----------------
__global__ void __launch_bounds__(256) k_out(const float* __restrict__ wO,
                                             const float* __restrict__ bO,
                                             const float* __restrict__ sRp,
                                             const float* __restrict__ sTp,
                                             float* __restrict__ out)
{
    int b = blockIdx.x;            // 512: n*64 + y
    int n = b >> 6, y = b & 63;
    __shared__ float  sR[HCc * Ww], sT[HCc * Ww], fu[HCc * Ww];
    __shared__ float4 wo[Cc * 4];  // wO rows as float4 pairs: wo[co*4+q]
    __shared__ float  bo[Cc];
    int t = threadIdx.x;

    const float* Rf = &g_F[0][n][0][0] + y * Ww;
    const float* Tf = &g_F[1][n][0][0] + y * Ww;
#pragma unroll
    for (int i = t; i < HCc * Ww; i += 256) {
        int hc = i >> 6, x = i & 63;
        sR[i] = Rf[hc * HWp + x];
        sT[i] = Tf[hc * HWp + x];
    }
    for (int i = t; i < Cc * 4; i += 256) wo[i] = ((const float4*)wO)[i];
    bo[t] = bO[t];
    float scR = sRp[0], scT = sTp[0];
    __syncthreads();

    int lane = t & 31, w = t >> 5;
#pragma unroll
    for (int hh = 0; hh < 2; hh++) {
        int hc = w + hh * 8;
        float rf0 = sR[hc * Ww + lane], rf1 = sR[hc * Ww + lane + 32];
        float tf0 = sT[hc * Ww + lane], tf1 = sT[hc * Ww + lane + 32];
        // softmax over W for R
        float a0 = rf0 * scR, a1 = rf1 * scR;
        float m = fmaxf(a0, a1);
#pragma unroll
        for (int o = 16; o; o >>= 1) m = fmaxf(m, __shfl_xor_sync(0xffffffffu, m, o));
        float e0 = expf(a0 - m), e1 = expf(a1 - m);
        float s = e0 + e1;
#pragma unroll
        for (int o = 16; o; o >>= 1) s += __shfl_xor_sync(0xffffffffu, s, o);
        float inv = 1.f / s;
        float mR0 = e0 * inv, mR1 = e1 * inv;
        // softmax over W for T
        float c0 = tf0 * scT, c1 = tf1 * scT;
        float mt = fmaxf(c0, c1);
#pragma unroll
        for (int o = 16; o; o >>= 1) mt = fmaxf(mt, __shfl_xor_sync(0xffffffffu, mt, o));
        float g0 = expf(c0 - mt), g1 = expf(c1 - mt);
        float st = g0 + g1;
#pragma unroll
        for (int o = 16; o; o >>= 1) st += __shfl_xor_sync(0xffffffffu, st, o);
        float invt = 1.f / st;
        float mT0 = g0 * invt, mT1 = g1 * invt;

        float wg = g_wG[n][hc];
        fu[hc * Ww + lane]      = mR0 * rf0 + mT0 * tf0 + wg * (rf0 + tf0);
        fu[hc * Ww + lane + 32] = mR1 * rf1 + mT1 * tf1 + wg * (rf1 + tf1);
    }
    __syncthreads();

    int x = t & 63, co0 = t >> 6;
    float fx[HCc];
#pragma unroll
    for (int i = 0; i < HCc; i++) fx[i] = fu[i * Ww + x];
    float* outp = out + (size_t)n * Cc * HWp + y * Ww + x;
    for (int co = co0; co < Cc; co += 4) {
        const float4* wp = &wo[co * 4];
        float a = bo[co];
#pragma unroll
        for (int q = 0; q < 4; q++) {
            float4 ww = wp[q];
            a += ww.x * fx[q*4+0] + ww.y * fx[q*4+1] + ww.z * fx[q*4+2] + ww.w * fx[q*4+3];
        }
        outp[(size_t)co * HWp] = a;
    }
}

// ---------------- launch ----------------
extern "C" void kernel_launch(void* const* d_in, const int* in_sizes, int n_in,
                              void* d_out, int out_size)
{
    const float* R      = (const float*)d_in[0];
    const float* T      = (const float*)d_in[1];
    const float* conv_w = (const float*)d_in[2];
    const float* bn_g   = (const float*)d_in[3];
    const float* bn_b   = (const float*)d_in[4];
    const float* bn_m   = (const float*)d_in[5];
    const float* bn_v   = (const float*)d_in[6];
    const float* f1W1   = (const float*)d_in[7];
    const float* f1b1   = (const float*)d_in[8];
    const float* f1W2R  = (const float*)d_in[9];
    const float* f1b2R  = (const float*)d_in[10];
    const float* f1W2T  = (const float*)d_in[11];
    const float* f1b2T  = (const float*)d_in[12];
    const float* f2W1   = (const float*)d_in[13];
    const float* f2b1   = (const float*)d_in[14];
    const float* f2W2R  = (const float*)d_in[15];
    const float* f2b2R  = (const float*)d_in[16];
    const float* f2W2T  = (const float*)d_in[17];
    const float* f2b2T  = (const float*)d_in[18];
    const float* fv_wR  = (const float*)d_in[19];
    const float* fv_bR  = (const float*)d_in[20];
    const float* fv_wT  = (const float*)d_in[21];
    const float* fv_bT  = (const float*)d_in[22];
    const float* fv_Lw  = (const float*)d_in[23];
    const float* fv_Lb  = (const float*)d_in[24];
    const float* fv_wO  = (const float*)d_in[25];
    const float* fv_bO  = (const float*)d_in[26];
    const float* fv_sR  = (const float*)d_in[27];
    const float* fv_sT  = (const float*)d_in[28];

    float* out  = (float*)d_out;
    float* outR = nullptr;
    float* outO = out;
    if (out_size >= 2 * NCHW) {   // output is (R, out) concatenated
        outR = out;
        outO = out + NCHW;
    }

    k_gap<<<4096, 128>>>(R, T, outR);
    k_vec<<<16, 256>>>(conv_w, bn_g, bn_b, bn_m, bn_v,
                       f1W1, f1b1, f1W2R, f1b2R, f1W2T, f1b2T,
                       f2W1, f2b1, f2W2R, f2b2R, f2W2T, f2b2T);
    k_main<<<128, 256>>>(R, T, fv_wR, fv_bR, fv_wT, fv_bT);
    k_wg<<<8, 256>>>(fv_Lw, fv_Lb);
    k_out<<<512, 256>>>(fv_wO, fv_bO, fv_sR, fv_sT, outO);
}

// round 3
// speedup vs baseline: 1.7056x; 1.7056x over previous
#include <cuda_runtime.h>
#include <cuda_bf16.h>
#include <cstdint>

// Problem constants
#define Nn   8
#define Cc   256
#define Hh   64
#define Ww   64
#define HWp  4096          // H*W
#define Gr   8             // groups
#define KK2  9             // K*K
#define GKK  72            // G*K*K
#define HIDc 256
#define HCc  16
#define NCHW (8*256*4096)
#define CSPLIT 4
#define CPB   (Cc/CSPLIT)   // 64 channels per block
#define NBLK_MAIN (2*Nn*8*CSPLIT)   // 512

// ---------------- scratch (device globals: no allocation allowed) ----------------
__device__ float  g_gap[2][Nn][Cc];              // per-modality GAP
__device__ float  g_filt[2][Nn][GKK];            // softmaxed dynamic filters
__device__ float2 g_wAB[2][Nn][Cc];              // (wR - wT, wT) gating per channel
__device__ float  g_Fp[2][CSPLIT][Nn][HCc][HWp]; // partial 16-ch features (no bias)
__device__ float  g_bsum[NBLK_MAIN][HCc];        // per-block partial sums for Gf mean
__device__ float  g_wG[Nn][HCc];                 // global gate

// ---------------- Kernel 1: GAP over H,W (+ copy R to output) ----------------
__global__ void k_gap(const float* __restrict__ R, const float* __restrict__ T,
                      float* __restrict__ outR)
{
    int b   = blockIdx.x;          // 0..4095 : mod*2048 + (n*256+c)
    int mod = b >> 11;
    int nc  = b & 2047;
    const float4* p = (const float4*)((mod ? T : R) + (size_t)nc * HWp);
    float4* q = (mod == 0 && outR) ? (float4*)(outR + (size_t)nc * HWp) : nullptr;
    int t = threadIdx.x;           // 128 threads
    float s = 0.f;
#pragma unroll
    for (int i = 0; i < 8; i++) {
        float4 v = p[t + 128 * i];
        if (q) q[t + 128 * i] = v;
        s += v.x + v.y + v.z + v.w;
    }
#pragma unroll
    for (int o = 16; o; o >>= 1) s += __shfl_down_sync(0xffffffffu, s, o);
    __shared__ float sm[4];
    if ((t & 31) == 0) sm[t >> 5] = s;
    __syncthreads();
    if (t == 0)
        g_gap[mod][nc >> 8][nc & 255] = (sm[0] + sm[1] + sm[2] + sm[3]) * (1.f / 4096.f);
}

// ---------------- Kernel 2: per-sample filters + gating MLPs ----------------
__global__ void k_vec(const float* __restrict__ conv_w,
                      const float* __restrict__ bn_g, const float* __restrict__ bn_b,
                      const float* __restrict__ bn_m, const float* __restrict__ bn_v,
                      const float* __restrict__ f1W1, const float* __restrict__ f1b1,
                      const float* __restrict__ f1W2R, const float* __restrict__ f1b2R,
                      const float* __restrict__ f1W2T, const float* __restrict__ f1b2T,
                      const float* __restrict__ f2W1, const float* __restrict__ f2b1,
                      const float* __restrict__ f2W2R, const float* __restrict__ f2b2R,
                      const float* __restrict__ f2W2T, const float* __restrict__ f2b2T)
{
    int mod = blockIdx.x >> 3, n = blockIdx.x & 7;
    const float* W1  = mod ? f2W1  : f1W1;
    const float* b1  = mod ? f2b1  : f1b1;
    const float* W2R = mod ? f2W2R : f1W2R;
    const float* b2R = mod ? f2b2R : f1b2R;
    const float* W2T = mod ? f2W2T : f1W2T;
    const float* b2T = mod ? f2b2T : f1b2T;

    __shared__ float gp[Cc], hid[HIDc], lf[GKK];
    int t = threadIdx.x;   // 256
    gp[t] = g_gap[mod][n][t];
    __syncthreads();

    if (t < GKK) {         // dynamic filter logits + BN
        float a = 0.f;
        for (int i = 0; i < Cc; i++) a += gp[i] * conv_w[t * Cc + i];
        a = (a - bn_m[t]) * rsqrtf(bn_v[t] + 1e-5f) * bn_g[t] + bn_b[t];
        lf[t] = a;
    }
    float a = b1[t];       // hidden layer (uses gap directly: (fl+fh).mean == gap)
    for (int i = 0; i < Cc; i++) a += gp[i] * W1[i * HIDc + t];
    hid[t] = fmaxf(a, 0.f);
    __syncthreads();

    if (t < Gr) {          // softmax over each group of 9
        float mx = -1e30f;
#pragma unroll
        for (int k = 0; k < KK2; k++) mx = fmaxf(mx, lf[t * KK2 + k]);
        float e[KK2], sum = 0.f;
#pragma unroll
        for (int k = 0; k < KK2; k++) { e[k] = expf(lf[t * KK2 + k] - mx); sum += e[k]; }
        float inv = 1.f / sum;
#pragma unroll
        for (int k = 0; k < KK2; k++) g_filt[mod][n][t * KK2 + k] = e[k] * inv;
    }
    float aR = b2R[t], aT = b2T[t];
    for (int i = 0; i < HIDc; i++) {
        float h = hid[i];
        aR += h * W2R[i * Cc + t];
        aT += h * W2T[i * Cc + t];
    }
    float wR = 1.f / (1.f + expf(-aR));
    float wT = 1.f / (1.f + expf(-aT));
    g_wAB[mod][n][t] = make_float2(wR - wT, wT);
}

// ---------------- Kernel 3: involution + gating + 256->16 conv (fused, split-C) ----
// grid = 512: (((mod*8 + n)*8 + tile)*4 + cs); tile: 2 (y) x 4 (x) of 32x16 pixel
// tiles; cs selects 64 channels. 256 threads, each owns 2 vertically-adjacent
// pixels. Double-buffered halo tile. Partial results (no bias) -> g_Fp; per-block
// per-hc sums -> g_bsum (deterministic, no atomics).
#define TSTRIDE 24
__global__ void __launch_bounds__(256, 3) k_main(const float* __restrict__ R,
                                                 const float* __restrict__ T,
                                                 const float* __restrict__ fv_wR,
                                                 const float* __restrict__ fv_wT)
{
    int b    = blockIdx.x;
    int cs   = b & 3;
    int r    = b >> 2;
    int tile = r & 7;
    r >>= 3;
    int n    = r & 7;
    int mod  = r >> 3;
    int ty0 = (tile >> 2) * 32;
    int tx0 = (tile & 3) * 16;

    const float* X    = (mod ? T : R) + (size_t)n * Cc * HWp + (size_t)cs * CPB * HWp;
    const float* wmat = mod ? fv_wT : fv_wR;      // [16][256]
    float* Out = &g_Fp[mod][cs][n][0][0];

    __shared__ float  buf[2][34 * TSTRIDE];
    __shared__ float  wv[CPB * HCc];       // transposed: wv[c*16+o], c local
    __shared__ float2 ab_sm[CPB];
    __shared__ float  filt_sm[2 * KK2];    // 2 groups per split
    __shared__ float  red[8][HCc];

    int t = threadIdx.x;
    for (int i = t; i < CPB * HCc; i += 256) {
        int o = i >> 6, c = i & 63;
        wv[c * HCc + o] = wmat[o * Cc + cs * CPB + c];
    }
    if (t < CPB) ab_sm[t] = g_wAB[mod][n][cs * CPB + t];
    if (t < 2 * KK2) filt_sm[t] = g_filt[mod][n][cs * 2 * KK2 + t];

    // precompute halo slots (34 rows x 18 cols = 612 loads)
    int goff[3], soff[3];
    bool has[3];
#pragma unroll
    for (int s = 0; s < 3; s++) {
        int idx = t + 256 * s;
        has[s] = idx < 612;
        int rr = idx / 18, qq = idx - rr * 18;
        int gy = ty0 - 1 + rr; gy = gy < 0 ? -gy : (gy > 63 ? 126 - gy : gy);
        int gx = tx0 - 1 + qq; gx = gx < 0 ? -gx : (gx > 63 ? 126 - gx : gx);
        goff[s] = gy * Ww + gx;
        soff[s] = rr * TSTRIDE + qq;
    }
    int tx = t & 15;
    int l  = (t >> 4) * 2;     // local y of first pixel (even)

    float acc0[HCc], acc1[HCc];
#pragma unroll
    for (int i = 0; i < HCc; i++) { acc0[i] = 0.f; acc1[i] = 0.f; }

    {   // preload channel 0 of this split
        const float* Xc = X;
#pragma unroll
        for (int s = 0; s < 3; s++) if (has[s]) buf[0][soff[s]] = Xc[goff[s]];
    }
    __syncthreads();

    float f[KK2];
    for (int c = 0; c < CPB; c++) {
        int p = c & 1;
        if (c + 1 < CPB) {
            const float* Xc = X + (size_t)(c + 1) * HWp;
#pragma unroll
            for (int s = 0; s < 3; s++) if (has[s]) buf[p ^ 1][soff[s]] = Xc[goff[s]];
        }
        if ((c & 31) == 0) {
            int gl = c >> 5;   // 0 or 1 within split
#pragma unroll
            for (int k = 0; k < KK2; k++) f[k] = filt_sm[gl * KK2 + k];
        }
        float2 ab = ab_sm[c];
        const float* w0 = &buf[p][l * TSTRIDE + tx];
        float v00 = w0[0],           v01 = w0[1],               v02 = w0[2];
        float v10 = w0[TSTRIDE],     v11 = w0[TSTRIDE + 1],     v12 = w0[TSTRIDE + 2];
        float v20 = w0[2 * TSTRIDE], v21 = w0[2 * TSTRIDE + 1], v22 = w0[2 * TSTRIDE + 2];
        float v30 = w0[3 * TSTRIDE], v31 = w0[3 * TSTRIDE + 1], v32 = w0[3 * TSTRIDE + 2];
        float low0 = f[0]*v00 + f[1]*v01 + f[2]*v02
                   + f[3]*v10 + f[4]*v11 + f[5]*v12
                   + f[6]*v20 + f[7]*v21 + f[8]*v22;
        float low1 = f[0]*v10 + f[1]*v11 + f[2]*v12
                   + f[3]*v20 + f[4]*v21 + f[5]*v22
                   + f[6]*v30 + f[7]*v31 + f[8]*v32;
        float val0 = ab.y * v11 + ab.x * low0;   // wT*X + (wR-wT)*low
        float val1 = ab.y * v21 + ab.x * low1;
        const float4* wp = (const float4*)&wv[c * HCc];
#pragma unroll
        for (int q = 0; q < 4; q++) {
            float4 w = wp[q];
            acc0[q*4+0] += w.x * val0; acc0[q*4+1] += w.y * val0;
            acc0[q*4+2] += w.z * val0; acc0[q*4+3] += w.w * val0;
            acc1[q*4+0] += w.x * val1; acc1[q*4+1] += w.y * val1;
            acc1[q*4+2] += w.z * val1; acc1[q*4+3] += w.w * val1;
        }
        __syncthreads();
    }

    // store partial outputs (no bias)
    int y0 = ty0 + l, x = tx0 + tx;
#pragma unroll
    for (int hc = 0; hc < HCc; hc++) {
        Out[hc * HWp + y0 * Ww + x]       = acc0[hc];
        Out[hc * HWp + (y0 + 1) * Ww + x] = acc1[hc];
    }

    // deterministic per-block reduction of tile sums for the Gf-mean path
    int lane = t & 31, w = t >> 5;
#pragma unroll
    for (int hc = 0; hc < HCc; hc++) {
        float v = acc0[hc] + acc1[hc];
#pragma unroll
        for (int o = 16; o; o >>= 1) v += __shfl_down_sync(0xffffffffu, v, o);
        if (lane == 0) red[w][hc] = v;
    }
    __syncthreads();
    if (t < HCc) {
        float s = 0.f;
#pragma unroll
        for (int ww = 0; ww < 8; ww++) s += red[ww][t];
        g_bsum[blockIdx.x][t] = s;
    }
}

// ---------------- Kernel 4: tiny Gf-mean gate ----------------
__global__ void k_wg2(const float* __restrict__ Lw, const float* __restrict__ Lb,
                      const float* __restrict__ bR, const float* __restrict__ bT)
{
    __shared__ float mean[Nn * HCc];
    int t = threadIdx.x;   // 128 : n*16 + hc
    int n = t >> 4, hc = t & 15;
    float s = 0.f;
#pragma unroll
    for (int mod = 0; mod < 2; mod++)
        for (int tile = 0; tile < 8; tile++)
            for (int cs = 0; cs < CSPLIT; cs++) {
                int idx = (((mod * Nn + n) * 8 + tile) << 2) + cs;
                s += g_bsum[idx][hc];
            }
    mean[t] = s * (1.f / 4096.f) + bR[hc] + bT[hc];
    __syncthreads();
    float a = Lb[hc];
#pragma unroll
    for (int i = 0; i < HCc; i++) a += mean[n * HCc + i] * Lw[i * HCc + hc];
    g_wG[n][hc] = 1.f / (1.f + expf(-a));
}

// ---------------- Kernel 5: fovea softmax (over W) + 16->256 conv ----------------
__global__ void __launch_bounds__(256) k_out(const float* __restrict__ wO,
                                             const float* __restrict__ bO,
                                             const float* __restrict__ sRp,
                                             const float* __restrict__ sTp,
                                             const float* __restrict__ bR,
                                             const float* __restrict__ bT,
                                             float* __restrict__ out)
{
    int b = blockIdx.x;            // 512: n*64 + y
    int n = b >> 6, y = b & 63;
    __shared__ float  sR[HCc * Ww], sT[HCc * Ww], fu[HCc * Ww];
    __shared__ float4 wo[Cc * 4];  // wO rows as float4: wo[co*4+q]
    __shared__ float  bo[Cc];
    int t = threadIdx.x;

#pragma unroll
    for (int i = t; i < HCc * Ww; i += 256) {
        int hc = i >> 6, x = i & 63;
        int off = hc * HWp + y * Ww + x;
        float r = bR[hc], tv = bT[hc];
#pragma unroll
        for (int cs = 0; cs < CSPLIT; cs++) {
            r  += g_Fp[0][cs][n][0][off];
            tv += g_Fp[1][cs][n][0][off];
        }
        sR[i] = r;
        sT[i] = tv;
    }
    for (int i = t; i < Cc * 4; i += 256) wo[i] = ((const float4*)wO)[i];
    bo[t] = bO[t];
    float scR = sRp[0], scT = sTp[0];
    __syncthreads();

    int lane = t & 31, w = t >> 5;
#pragma unroll
    for (int hh = 0; hh < 2; hh++) {
        int hc = w + hh * 8;
        float rf0 = sR[hc * Ww + lane], rf1 = sR[hc * Ww + lane + 32];
        float tf0 = sT[hc * Ww + lane], tf1 = sT[hc * Ww + lane + 32];
        float a0 = rf0 * scR, a1 = rf1 * scR;
        float m = fmaxf(a0, a1);
#pragma unroll
        for (int o = 16; o; o >>= 1) m = fmaxf(m, __shfl_xor_sync(0xffffffffu, m, o));
        float e0 = expf(a0 - m), e1 = expf(a1 - m);
        float s = e0 + e1;
#pragma unroll
        for (int o = 16; o; o >>= 1) s += __shfl_xor_sync(0xffffffffu, s, o);
        float inv = 1.f / s;
        float mR0 = e0 * inv, mR1 = e1 * inv;
        float c0 = tf0 * scT, c1 = tf1 * scT;
        float mt = fmaxf(c0, c1);
#pragma unroll
        for (int o = 16; o; o >>= 1) mt = fmaxf(mt, __shfl_xor_sync(0xffffffffu, mt, o));
        float g0 = expf(c0 - mt), g1 = expf(c1 - mt);
        float st = g0 + g1;
#pragma unroll
        for (int o = 16; o; o >>= 1) st += __shfl_xor_sync(0xffffffffu, st, o);
        float invt = 1.f / st;
        float mT0 = g0 * invt, mT1 = g1 * invt;

        float wg = g_wG[n][hc];
        fu[hc * Ww + lane]      = mR0 * rf0 + mT0 * tf0 + wg * (rf0 + tf0);
        fu[hc * Ww + lane + 32] = mR1 * rf1 + mT1 * tf1 + wg * (rf1 + tf1);
    }
    __syncthreads();

    int x = t & 63, co0 = t >> 6;
    float fx[HCc];
#pragma unroll
    for (int i = 0; i < HCc; i++) fx[i] = fu[i * Ww + x];
    float* outp = out + (size_t)n * Cc * HWp + y * Ww + x;
    for (int co = co0; co < Cc; co += 4) {
        const float4* wp = &wo[co * 4];
        float a = bo[co];
#pragma unroll
        for (int q = 0; q < 4; q++) {
            float4 ww = wp[q];
            a += ww.x * fx[q*4+0] + ww.y * fx[q*4+1] + ww.z * fx[q*4+2] + ww.w * fx[q*4+3];
        }
        outp[(size_t)co * HWp] = a;
    }
}

// ---------------- launch ----------------
extern "C" void kernel_launch(void* const* d_in, const int* in_sizes, int n_in,
                              void* d_out, int out_size)
{
    const float* R      = (const float*)d_in[0];
    const float* T      = (const float*)d_in[1];
    const float* conv_w = (const float*)d_in[2];
    const float* bn_g   = (const float*)d_in[3];
    const float* bn_b   = (const float*)d_in[4];
    const float* bn_m   = (const float*)d_in[5];
    const float* bn_v   = (const float*)d_in[6];
    const float* f1W1   = (const float*)d_in[7];
    const float* f1b1   = (const float*)d_in[8];
    const float* f1W2R  = (const float*)d_in[9];
    const float* f1b2R  = (const float*)d_in[10];
    const float* f1W2T  = (const float*)d_in[11];
    const float* f1b2T  = (const float*)d_in[12];
    const float* f2W1   = (const float*)d_in[13];
    const float* f2b1   = (const float*)d_in[14];
    const float* f2W2R  = (const float*)d_in[15];
    const float* f2b2R  = (const float*)d_in[16];
    const float* f2W2T  = (const float*)d_in[17];
    const float* f2b2T  = (const float*)d_in[18];
    const float* fv_wR  = (const float*)d_in[19];
    const float* fv_bR  = (const float*)d_in[20];
    const float* fv_wT  = (const float*)d_in[21];
    const float* fv_bT  = (const float*)d_in[22];
    const float* fv_Lw  = (const float*)d_in[23];
    const float* fv_Lb  = (const float*)d_in[24];
    const float* fv_wO  = (const float*)d_in[25];
    const float* fv_bO  = (const float*)d_in[26];
    const float* fv_sR  = (const float*)d_in[27];
    const float* fv_sT  = (const float*)d_in[28];

    float* out  = (float*)d_out;
    float* outR = nullptr;
    float* outO = out;
    if (out_size >= 2 * NCHW) {   // output is (R, out) concatenated
        outR = out;
        outO = out + NCHW;
    }

    k_gap<<<4096, 128>>>(R, T, outR);
    k_vec<<<16, 256>>>(conv_w, bn_g, bn_b, bn_m, bn_v,
                       f1W1, f1b1, f1W2R, f1b2R, f1W2T, f1b2T,
                       f2W1, f2b1, f2W2R, f2b2R, f2W2T, f2b2T);
    k_main<<<NBLK_MAIN, 256>>>(R, T, fv_wR, fv_wT);
    k_wg2<<<1, 128>>>(fv_Lw, fv_Lb, fv_bR, fv_bT);
    k_out<<<512, 256>>>(fv_wO, fv_bO, fv_sR, fv_sT, fv_bR, fv_bT, outO);
}